// round 3
// baseline (speedup 1.0000x reference)
#include <cuda_runtime.h>
#include <math.h>

#define NTOK 2048
#define DDIM 1024
#define FDIM 4096
#define NE 8
#define LN_EPS 1e-5f

#define BM 128
#define BN 64
#define BK 16
// Padded-row capacity: sum over experts of ceil(cnt/BM)*BM < 2048 + 8*BM = 3072
#define CAPROWS 3072
#define RTILES (CAPROWS / BM)

// __device__ scratch (no allocation allowed)
__device__ float g_xg[(size_t)CAPROWS * DDIM];   // grouped, normalized+affine tokens
__device__ float g_act[(size_t)CAPROWS * FDIM];  // relu(h@w1+b1)
__device__ float g_alpha[NTOK];
__device__ float g_mu[NTOK];
__device__ float g_rs[NTOK];
__device__ int   g_eid[NTOK];
__device__ int   g_rank[NTOK];
__device__ int   g_cnt[NE];
__device__ int   g_off[NE + 1];
__device__ int   g_tok[CAPROWS];

__global__ void init_kernel() {
    if (threadIdx.x < NE) g_cnt[threadIdx.x] = 0;
}

// One block per token: centroid affinities (argmax + sigmoid gate) + LN stats.
__global__ __launch_bounds__(256) void router_kernel(const float* __restrict__ x,
                                                     const float* __restrict__ cent) {
    int t = blockIdx.x;
    int tid = threadIdx.x;
    float4 v = ((const float4*)(x + (size_t)t * DDIM))[tid];
    float vals[10];
    vals[0] = v.x + v.y + v.z + v.w;                       // sum
    vals[1] = v.x*v.x + v.y*v.y + v.z*v.z + v.w*v.w;       // sumsq
#pragma unroll
    for (int e = 0; e < NE; e++) {
        float4 c = ((const float4*)(cent + (size_t)e * DDIM))[tid];
        vals[2 + e] = v.x*c.x + v.y*c.y + v.z*c.z + v.w*c.w;
    }
#pragma unroll
    for (int off = 16; off > 0; off >>= 1) {
#pragma unroll
        for (int i = 0; i < 10; i++)
            vals[i] += __shfl_down_sync(0xffffffffu, vals[i], off);
    }
    __shared__ float red[8][10];
    int warp = tid >> 5, lane = tid & 31;
    if (lane == 0) {
#pragma unroll
        for (int i = 0; i < 10; i++) red[warp][i] = vals[i];
    }
    __syncthreads();
    if (tid < 10) {
        float s = 0.f;
#pragma unroll
        for (int w = 0; w < 8; w++) s += red[w][tid];
        red[0][tid] = s;
    }
    __syncthreads();
    if (tid == 0) {
        float sum = red[0][0], ss = red[0][1];
        int best = 0;
        float bv = red[0][2];
#pragma unroll
        for (int e = 1; e < NE; e++) {
            float a = red[0][2 + e];
            if (a > bv) { bv = a; best = e; }   // strict > keeps first-max (jnp.argmax)
        }
        float mu = sum * (1.0f / DDIM);
        float var = ss * (1.0f / DDIM) - mu * mu;
        g_mu[t] = mu;
        g_rs[t] = rsqrtf(var + LN_EPS);
        g_eid[t] = best;
        g_alpha[t] = 1.0f / (1.0f + expf(-bv));
        g_rank[t] = atomicAdd(&g_cnt[best], 1);
    }
}

// Exclusive padded offsets so each 128-row GEMM tile is single-expert.
__global__ void offsets_kernel() {
    int o = 0;
#pragma unroll
    for (int e = 0; e < NE; e++) {
        g_off[e] = o;
        o += ((g_cnt[e] + BM - 1) / BM) * BM;
    }
    g_off[NE] = o;
}

// Gather tokens into per-expert compacted rows; apply LN + per-expert affine.
__global__ __launch_bounds__(256) void scatter_kernel(const float* __restrict__ x,
                                                      const float* __restrict__ gamma,
                                                      const float* __restrict__ beta) {
    int t = blockIdx.x, tid = threadIdx.x;
    int e = g_eid[t];
    int slot = g_off[e] + g_rank[t];
    float mu = g_mu[t], rs = g_rs[t];
    float4 v = ((const float4*)(x + (size_t)t * DDIM))[tid];
    float4 g = ((const float4*)(gamma + (size_t)e * DDIM))[tid];
    float4 b = ((const float4*)(beta + (size_t)e * DDIM))[tid];
    float4 o;
    o.x = (v.x - mu) * rs * g.x + b.x;
    o.y = (v.y - mu) * rs * g.y + b.y;
    o.z = (v.z - mu) * rs * g.z + b.z;
    o.w = (v.w - mu) * rs * g.w + b.w;
    ((float4*)(g_xg + (size_t)slot * DDIM))[tid] = o;
    if (tid == 0) g_tok[slot] = t;
}

// Double-buffered fp32 SGEMM, 128x64 tile, BK=16, 8x4 per-thread fragment.
// MODE 0: g_act = relu(g_xg @ w1[e] + b1[e])          (K=1024, N=4096)
// MODE 1: out[t] = x[t] + alpha[t]*(g_act @ w2[e] + b2[e])  (K=4096, N=1024)
template <int MODE>
__global__ __launch_bounds__(256) void gemm_kernel(const float* __restrict__ W,
                                                   const float* __restrict__ bias,
                                                   const float* __restrict__ xin,
                                                   float* __restrict__ dout) {
    constexpr int K = (MODE == 0) ? DDIM : FDIM;
    constexpr int N = (MODE == 0) ? FDIM : DDIM;

    int total = g_off[NE];
    int r0 = blockIdx.y * BM;
    if (r0 >= total) return;
    int e = 0;
    while (g_off[e + 1] <= r0) e++;
    int n0 = blockIdx.x * BN;

    const float* A = (MODE == 0) ? g_xg : g_act;
    A += (size_t)r0 * K;
    const float* B = W + (size_t)e * K * N;

    __shared__ float As[2][BK][BM + 4];   // transposed A tile, padded (16B-aligned rows)
    __shared__ float Bs[2][BK][BN];

    int tid = threadIdx.x;
    int tx = tid & 15, ty = tid >> 4;
    int arow = tid >> 2;            // 0..63, second row = arow+64
    int akc = (tid & 3) << 2;       // k sub-offset 0/4/8/12
    int brow = tid >> 4;            // 0..15
    int bcol = (tid & 15) << 2;     // 0..60

    float acc[8][4];
#pragma unroll
    for (int i = 0; i < 8; i++)
#pragma unroll
        for (int j = 0; j < 4; j++) acc[i][j] = 0.f;

    // prologue: tile 0 -> shared[0]
    {
        float4 a0 = *(const float4*)(A + (size_t)arow * K + akc);
        float4 a1 = *(const float4*)(A + (size_t)(arow + 64) * K + akc);
        As[0][akc + 0][arow] = a0.x; As[0][akc + 1][arow] = a0.y;
        As[0][akc + 2][arow] = a0.z; As[0][akc + 3][arow] = a0.w;
        As[0][akc + 0][arow + 64] = a1.x; As[0][akc + 1][arow + 64] = a1.y;
        As[0][akc + 2][arow + 64] = a1.z; As[0][akc + 3][arow + 64] = a1.w;
        float4 b = *(const float4*)(B + (size_t)brow * N + n0 + bcol);
        *(float4*)&Bs[0][brow][bcol] = b;
    }
    __syncthreads();

    constexpr int NKT = K / BK;
    int buf = 0;
    for (int kt = 0; kt < NKT; kt++) {
        float4 pa0, pa1, pb;
        if (kt + 1 < NKT) {
            int kb = (kt + 1) * BK;
            pa0 = *(const float4*)(A + (size_t)arow * K + kb + akc);
            pa1 = *(const float4*)(A + (size_t)(arow + 64) * K + kb + akc);
            pb  = *(const float4*)(B + (size_t)(kb + brow) * N + n0 + bcol);
        }
#pragma unroll
        for (int k = 0; k < BK; k++) {
            float4 af0 = *(const float4*)&As[buf][k][ty * 8];
            float4 af1 = *(const float4*)&As[buf][k][ty * 8 + 4];
            float4 bf  = *(const float4*)&Bs[buf][k][tx * 4];
            float av[8] = {af0.x, af0.y, af0.z, af0.w, af1.x, af1.y, af1.z, af1.w};
            float bw[4] = {bf.x, bf.y, bf.z, bf.w};
#pragma unroll
            for (int i = 0; i < 8; i++)
#pragma unroll
                for (int j = 0; j < 4; j++)
                    acc[i][j] = fmaf(av[i], bw[j], acc[i][j]);
        }
        if (kt + 1 < NKT) {
            int nb = buf ^ 1;
            As[nb][akc + 0][arow] = pa0.x; As[nb][akc + 1][arow] = pa0.y;
            As[nb][akc + 2][arow] = pa0.z; As[nb][akc + 3][arow] = pa0.w;
            As[nb][akc + 0][arow + 64] = pa1.x; As[nb][akc + 1][arow + 64] = pa1.y;
            As[nb][akc + 2][arow + 64] = pa1.z; As[nb][akc + 3][arow + 64] = pa1.w;
            *(float4*)&Bs[nb][brow][bcol] = pb;
            __syncthreads();
            buf = nb;
        }
    }

    if (MODE == 0) {
        float4 bsv = *(const float4*)(bias + (size_t)e * N + n0 + tx * 4);
#pragma unroll
        for (int i = 0; i < 8; i++) {
            int row = r0 + ty * 8 + i;
            float4 o;
            o.x = fmaxf(acc[i][0] + bsv.x, 0.f);
            o.y = fmaxf(acc[i][1] + bsv.y, 0.f);
            o.z = fmaxf(acc[i][2] + bsv.z, 0.f);
            o.w = fmaxf(acc[i][3] + bsv.w, 0.f);
            *(float4*)(g_act + (size_t)row * N + n0 + tx * 4) = o;
        }
    } else {
        int cnt = g_cnt[e];
        int base = g_off[e];
        float4 bsv = *(const float4*)(bias + (size_t)e * N + n0 + tx * 4);
#pragma unroll
        for (int i = 0; i < 8; i++) {
            int row = r0 + ty * 8 + i;
            if (row - base < cnt) {
                int t = g_tok[row];
                float al = g_alpha[t];
                float4 xv = *(const float4*)(xin + (size_t)t * DDIM + n0 + tx * 4);
                float4 o;
                o.x = xv.x + al * (acc[i][0] + bsv.x);
                o.y = xv.y + al * (acc[i][1] + bsv.y);
                o.z = xv.z + al * (acc[i][2] + bsv.z);
                o.w = xv.w + al * (acc[i][3] + bsv.w);
                *(float4*)(dout + (size_t)t * DDIM + n0 + tx * 4) = o;
            }
        }
    }
}

extern "C" void kernel_launch(void* const* d_in, const int* in_sizes, int n_in,
                              void* d_out, int out_size) {
    const float* x     = (const float*)d_in[0];
    const float* cent  = (const float*)d_in[1];
    const float* w1    = (const float*)d_in[2];
    const float* b1    = (const float*)d_in[3];
    const float* w2    = (const float*)d_in[4];
    const float* b2    = (const float*)d_in[5];
    const float* gamma = (const float*)d_in[6];
    const float* beta  = (const float*)d_in[7];
    float* out = (float*)d_out;

    init_kernel<<<1, 32>>>();
    router_kernel<<<NTOK, 256>>>(x, cent);
    offsets_kernel<<<1, 1>>>();
    scatter_kernel<<<NTOK, 256>>>(x, gamma, beta);
    gemm_kernel<0><<<dim3(FDIM / BN, RTILES), 256>>>(w1, b1, nullptr, nullptr);
    gemm_kernel<1><<<dim3(DDIM / BN, RTILES), 256>>>(w2, b2, x, out);
}

// round 10
// speedup vs baseline: 2.6088x; 2.6088x over previous
#include <cuda_runtime.h>
#include <cuda_bf16.h>
#include <math.h>
#include <stdint.h>

#define NTOK 2048
#define DDIM 1024
#define FDIM 4096
#define NE 8
#define LN_EPS 1e-5f
#define PADROWS 128
#define CAPROWS 3072
#define RTILES (CAPROWS / PADROWS)
#define ZSPLIT 2
// smem layout (bytes): A hi/lo: 128 rows x 72 bf16 (pad 8) = 18432 each
// B hi/lo: 64 rows x 136 bf16 (pad 8) = 17408 each; double buffered
#define OAH(b) ((b) * 36864)
#define OAL(b) ((b) * 36864 + 18432)
#define OBH(b) (73728 + (b) * 34816)
#define OBL(b) (73728 + (b) * 34816 + 17408)
#define SMEM_TOTAL 143360

__device__ uint32_t g_xg_hi[(size_t)CAPROWS * DDIM / 2];
__device__ uint32_t g_xg_lo[(size_t)CAPROWS * DDIM / 2];
__device__ uint32_t g_act_hi[(size_t)CAPROWS * FDIM / 2];
__device__ uint32_t g_act_lo[(size_t)CAPROWS * FDIM / 2];
__device__ float    g_part[ZSPLIT][(size_t)CAPROWS * DDIM];
__device__ float    g_alpha[NTOK];
__device__ float    g_mu[NTOK];
__device__ float    g_rs[NTOK];
__device__ int      g_eid[NTOK];
__device__ int      g_rank[NTOK];
__device__ int      g_cnt[NE];
__device__ int      g_off[NE + 1];

__device__ __forceinline__ uint32_t smem_u32(const void* p) {
    uint32_t a;
    asm("{ .reg .u64 t; cvta.to.shared.u64 t, %1; cvt.u32.u64 %0, t; }" : "=r"(a) : "l"(p));
    return a;
}
#define LDSM4(R, addr) \
    asm volatile("ldmatrix.sync.aligned.m8n8.x4.shared.b16 {%0,%1,%2,%3},[%4];" \
                 : "=r"((R)[0]), "=r"((R)[1]), "=r"((R)[2]), "=r"((R)[3]) : "r"(addr))
#define LDSM4T(R, addr) \
    asm volatile("ldmatrix.sync.aligned.m8n8.x4.trans.shared.b16 {%0,%1,%2,%3},[%4];" \
                 : "=r"((R)[0]), "=r"((R)[1]), "=r"((R)[2]), "=r"((R)[3]) : "r"(addr))
#define MMA16816(C, A, b0, b1) \
    asm volatile("mma.sync.aligned.m16n8k16.row.col.f32.bf16.bf16.f32 " \
                 "{%0,%1,%2,%3},{%4,%5,%6,%7},{%8,%9},{%0,%1,%2,%3};" \
                 : "+f"((C)[0]), "+f"((C)[1]), "+f"((C)[2]), "+f"((C)[3]) \
                 : "r"((A)[0]), "r"((A)[1]), "r"((A)[2]), "r"((A)[3]), "r"(b0), "r"(b1))
#define CPASYNC16(s, g) \
    asm volatile("cp.async.cg.shared.global [%0],[%1],16;" :: "r"(s), \
                 "l"((unsigned long long)__cvta_generic_to_global(g)) : "memory")
#define CPCOMMIT() asm volatile("cp.async.commit_group;" ::: "memory")

__device__ __forceinline__ void split2(float a, float b, uint32_t& hi, uint32_t& lo) {
    __nv_bfloat16 ha = __float2bfloat16(a), hb = __float2bfloat16(b);
    __nv_bfloat16 la = __float2bfloat16(a - __bfloat162float(ha));
    __nv_bfloat16 lb = __float2bfloat16(b - __bfloat162float(hb));
    hi = (uint32_t)__bfloat16_as_ushort(ha) | ((uint32_t)__bfloat16_as_ushort(hb) << 16);
    lo = (uint32_t)__bfloat16_as_ushort(la) | ((uint32_t)__bfloat16_as_ushort(lb) << 16);
}

__global__ void init_kernel() { if (threadIdx.x < NE) g_cnt[threadIdx.x] = 0; }

__global__ __launch_bounds__(256) void router_kernel(const float* __restrict__ x,
                                                     const float* __restrict__ cent) {
    int t = blockIdx.x, tid = threadIdx.x;
    float4 v = ((const float4*)(x + (size_t)t * DDIM))[tid];
    float vals[10];
    vals[0] = v.x + v.y + v.z + v.w;
    vals[1] = v.x*v.x + v.y*v.y + v.z*v.z + v.w*v.w;
#pragma unroll
    for (int e = 0; e < NE; e++) {
        float4 c = ((const float4*)(cent + (size_t)e * DDIM))[tid];
        vals[2 + e] = v.x*c.x + v.y*c.y + v.z*c.z + v.w*c.w;
    }
#pragma unroll
    for (int off = 16; off > 0; off >>= 1)
#pragma unroll
        for (int i = 0; i < 10; i++)
            vals[i] += __shfl_down_sync(0xffffffffu, vals[i], off);
    __shared__ float red[8][10];
    int warp = tid >> 5, lane = tid & 31;
    if (lane == 0)
#pragma unroll
        for (int i = 0; i < 10; i++) red[warp][i] = vals[i];
    __syncthreads();
    if (tid < 10) {
        float s = 0.f;
#pragma unroll
        for (int w = 0; w < 8; w++) s += red[w][tid];
        red[0][tid] = s;
    }
    __syncthreads();
    if (tid == 0) {
        float sum = red[0][0], ss = red[0][1];
        int best = 0; float bv = red[0][2];
#pragma unroll
        for (int e = 1; e < NE; e++) {
            float a = red[0][2 + e];
            if (a > bv) { bv = a; best = e; }
        }
        float mu = sum * (1.0f / DDIM);
        float var = ss * (1.0f / DDIM) - mu * mu;
        g_mu[t] = mu; g_rs[t] = rsqrtf(var + LN_EPS);
        g_eid[t] = best;
        g_alpha[t] = 1.0f / (1.0f + expf(-bv));
        g_rank[t] = atomicAdd(&g_cnt[best], 1);
    }
}

__global__ void offsets_kernel() {
    int o = 0;
#pragma unroll
    for (int e = 0; e < NE; e++) {
        g_off[e] = o;
        o += ((g_cnt[e] + PADROWS - 1) / PADROWS) * PADROWS;
    }
    g_off[NE] = o;
}

__global__ __launch_bounds__(256) void scatter_kernel(const float* __restrict__ x,
                                                      const float* __restrict__ gamma,
                                                      const float* __restrict__ beta) {
    int t = blockIdx.x, tid = threadIdx.x;
    int e = g_eid[t];
    int slot = g_off[e] + g_rank[t];
    float mu = g_mu[t], rs = g_rs[t];
    float4 v = ((const float4*)(x + (size_t)t * DDIM))[tid];
    float4 g = ((const float4*)(gamma + (size_t)e * DDIM))[tid];
    float4 b = ((const float4*)(beta + (size_t)e * DDIM))[tid];
    float o0 = (v.x - mu) * rs * g.x + b.x;
    float o1 = (v.y - mu) * rs * g.y + b.y;
    float o2 = (v.z - mu) * rs * g.z + b.z;
    float o3 = (v.w - mu) * rs * g.w + b.w;
    uint32_t h0, l0, h1, l1;
    split2(o0, o1, h0, l0);
    split2(o2, o3, h1, l1);
    ((uint2*)g_xg_hi)[(size_t)slot * 256 + tid] = make_uint2(h0, h1);
    ((uint2*)g_xg_lo)[(size_t)slot * 256 + tid] = make_uint2(l0, l1);
}

// 128x128 CTA tile, 8 warps each 64x32, K-chunk 64, split-bf16 3-term mma.sync.
// MODE 0: g_act = relu(g_xg @ w1[e] + b1[e])   K=1024, N=4096
// MODE 1: g_part[z] = g_act @ w2[e]  (K slice) K=2048/z, N=1024
template <int MODE>
__global__ __launch_bounds__(256) void gemm_mma(const float* __restrict__ W,
                                                const float* __restrict__ bias) {
    constexpr int K = MODE ? FDIM : DDIM;
    constexpr int N = MODE ? DDIM : FDIM;
    constexpr int NCH = (MODE ? FDIM / ZSPLIT : DDIM) / 64;
    extern __shared__ char smem[];
    uint32_t sbase = smem_u32(smem);

    int r0 = blockIdx.y * 128;
    if (r0 >= g_off[NE]) return;
    int e = 0;
    while (g_off[e + 1] <= r0) e++;
    int n0 = blockIdx.x * 128;
    int kz = MODE ? blockIdx.z * (FDIM / ZSPLIT) : 0;

    int tid = threadIdx.x, lane = tid & 31, warp = tid >> 5;
    int wm = warp >> 2, wn = warp & 3;

    const uint4* Ah = (const uint4*)(MODE ? g_act_hi : g_xg_hi);
    const uint4* Al = (const uint4*)(MODE ? g_act_lo : g_xg_lo);
    const float* Wexp = W + (size_t)e * K * N;

    float acc[4][4][4];
#pragma unroll
    for (int i = 0; i < 4; i++)
#pragma unroll
        for (int j = 0; j < 4; j++)
#pragma unroll
            for (int q = 0; q < 4; q++) acc[i][j][q] = 0.f;

    int brr = tid >> 5, bf4 = tid & 31;
    float4 bpre[8];

    // prologue: A chunk0 via cp.async, B chunk0 to regs
    {
#pragma unroll
        for (int p = 0; p < 4; p++) {
            int idx = p * 256 + tid; int arow = idx >> 3; int ac8 = idx & 7;
            size_t gi = (size_t)(r0 + arow) * (K / 8) + (kz >> 3) + ac8;
            CPASYNC16(sbase + OAH(0) + arow * 144 + ac8 * 16, Ah + gi);
            CPASYNC16(sbase + OAL(0) + arow * 144 + ac8 * 16, Al + gi);
        }
        CPCOMMIT();
#pragma unroll
        for (int p = 0; p < 8; p++)
            bpre[p] = *(const float4*)(Wexp + (size_t)(kz + brr + p * 8) * N + n0 + bf4 * 4);
    }

    for (int ch = 0; ch < NCH; ch++) {
        int b = ch & 1;
        // store B regs (split fp32 -> bf16 hi/lo) into smem buffer b
#pragma unroll
        for (int p = 0; p < 8; p++) {
            int row = brr + p * 8;
            uint32_t h0, l0, h1, l1;
            split2(bpre[p].x, bpre[p].y, h0, l0);
            split2(bpre[p].z, bpre[p].w, h1, l1);
            *(uint2*)(smem + OBH(b) + row * 272 + bf4 * 8) = make_uint2(h0, h1);
            *(uint2*)(smem + OBL(b) + row * 272 + bf4 * 8) = make_uint2(l0, l1);
        }
        if (ch + 1 < NCH) {
            int kc = kz + (ch + 1) * 64;
#pragma unroll
            for (int p = 0; p < 4; p++) {
                int idx = p * 256 + tid; int row = idx >> 3; int c8 = idx & 7;
                size_t gi = (size_t)(r0 + row) * (K / 8) + (kc >> 3) + c8;
                CPASYNC16(sbase + OAH(b ^ 1) + row * 144 + c8 * 16, Ah + gi);
                CPASYNC16(sbase + OAL(b ^ 1) + row * 144 + c8 * 16, Al + gi);
            }
            CPCOMMIT();
#pragma unroll
            for (int p = 0; p < 8; p++)
                bpre[p] = *(const float4*)(Wexp + (size_t)(kc + brr + p * 8) * N + n0 + bf4 * 4);
            asm volatile("cp.async.wait_group 1;" ::: "memory");
        } else {
            asm volatile("cp.async.wait_group 0;" ::: "memory");
        }
        __syncthreads();

        // compute chunk (4 k16 steps)
        uint32_t aAh = sbase + OAH(b), aAl = sbase + OAL(b);
        uint32_t aBh = sbase + OBH(b), aBl = sbase + OBL(b);
#pragma unroll
        for (int ks = 0; ks < 4; ks++) {
            uint32_t ahi[4][4], alo[4][4];
#pragma unroll
            for (int mf = 0; mf < 4; mf++) {
                int row = wm * 64 + mf * 16 + (lane & 15);
                int cb = ks * 32 + (lane >> 4) * 16;
                LDSM4(ahi[mf], aAh + row * 144 + cb);
                LDSM4(alo[mf], aAl + row * 144 + cb);
            }
            uint32_t bhi[2][4], blo[2][4];
#pragma unroll
            for (int g = 0; g < 2; g++) {
                int krow = ks * 16 + (lane & 15);
                int nc = wn * 32 + g * 16 + (lane >> 4) * 8;
                LDSM4T(bhi[g], aBh + krow * 272 + nc * 2);
                LDSM4T(blo[g], aBl + krow * 272 + nc * 2);
            }
#pragma unroll
            for (int mf = 0; mf < 4; mf++)
#pragma unroll
                for (int nf = 0; nf < 4; nf++) {
                    int g = nf >> 1, j = (nf & 1) * 2;
                    MMA16816(acc[mf][nf], ahi[mf], bhi[g][j], bhi[g][j + 1]);
                    MMA16816(acc[mf][nf], ahi[mf], blo[g][j], blo[g][j + 1]);
                    MMA16816(acc[mf][nf], alo[mf], bhi[g][j], bhi[g][j + 1]);
                }
        }
        __syncthreads();
    }

    // epilogue
    int gr = lane >> 2, gc = (lane & 3) * 2;
    if (MODE == 0) {
        const float* be = bias + (size_t)e * N;
#pragma unroll
        for (int mf = 0; mf < 4; mf++)
#pragma unroll
            for (int nf = 0; nf < 4; nf++) {
                int row = r0 + wm * 64 + mf * 16 + gr;
                int col = n0 + wn * 32 + nf * 8 + gc;
                float b0v = be[col], b1v = be[col + 1];
                uint32_t h, l;
                float v0 = fmaxf(acc[mf][nf][0] + b0v, 0.f);
                float v1 = fmaxf(acc[mf][nf][1] + b1v, 0.f);
                split2(v0, v1, h, l);
                g_act_hi[(size_t)row * (FDIM / 2) + (col >> 1)] = h;
                g_act_lo[(size_t)row * (FDIM / 2) + (col >> 1)] = l;
                float v2 = fmaxf(acc[mf][nf][2] + b0v, 0.f);
                float v3 = fmaxf(acc[mf][nf][3] + b1v, 0.f);
                split2(v2, v3, h, l);
                g_act_hi[(size_t)(row + 8) * (FDIM / 2) + (col >> 1)] = h;
                g_act_lo[(size_t)(row + 8) * (FDIM / 2) + (col >> 1)] = l;
            }
    } else {
        float* part = g_part[blockIdx.z];
#pragma unroll
        for (int mf = 0; mf < 4; mf++)
#pragma unroll
            for (int nf = 0; nf < 4; nf++) {
                int row = r0 + wm * 64 + mf * 16 + gr;
                int col = n0 + wn * 32 + nf * 8 + gc;
                *(float2*)(part + (size_t)row * DDIM + col) =
                    make_float2(acc[mf][nf][0], acc[mf][nf][1]);
                *(float2*)(part + (size_t)(row + 8) * DDIM + col) =
                    make_float2(acc[mf][nf][2], acc[mf][nf][3]);
            }
    }
}

__global__ __launch_bounds__(256) void finalize_kernel(const float* __restrict__ x,
                                                       const float* __restrict__ b2,
                                                       float* __restrict__ out) {
    int t = blockIdx.x, tid = threadIdx.x;
    int e = g_eid[t];
    int slot = g_off[e] + g_rank[t];
    float al = g_alpha[t];
    float4 xv = ((const float4*)(x + (size_t)t * DDIM))[tid];
    float4 bv = ((const float4*)(b2 + (size_t)e * DDIM))[tid];
    float4 s = make_float4(0.f, 0.f, 0.f, 0.f);
#pragma unroll
    for (int z = 0; z < ZSPLIT; z++) {
        float4 p = ((const float4*)(g_part[z] + (size_t)slot * DDIM))[tid];
        s.x += p.x; s.y += p.y; s.z += p.z; s.w += p.w;
    }
    float4 o;
    o.x = xv.x + al * (s.x + bv.x);
    o.y = xv.y + al * (s.y + bv.y);
    o.z = xv.z + al * (s.z + bv.z);
    o.w = xv.w + al * (s.w + bv.w);
    ((float4*)(out + (size_t)t * DDIM))[tid] = o;
}

extern "C" void kernel_launch(void* const* d_in, const int* in_sizes, int n_in,
                              void* d_out, int out_size) {
    const float* x     = (const float*)d_in[0];
    const float* cent  = (const float*)d_in[1];
    const float* w1    = (const float*)d_in[2];
    const float* b1    = (const float*)d_in[3];
    const float* w2    = (const float*)d_in[4];
    const float* b2    = (const float*)d_in[5];
    const float* gamma = (const float*)d_in[6];
    const float* beta  = (const float*)d_in[7];
    float* out = (float*)d_out;

    cudaFuncSetAttribute(gemm_mma<0>, cudaFuncAttributeMaxDynamicSharedMemorySize, SMEM_TOTAL);
    cudaFuncSetAttribute(gemm_mma<1>, cudaFuncAttributeMaxDynamicSharedMemorySize, SMEM_TOTAL);

    init_kernel<<<1, 32>>>();
    router_kernel<<<NTOK, 256>>>(x, cent);
    offsets_kernel<<<1, 1>>>();
    scatter_kernel<<<NTOK, 256>>>(x, gamma, beta);
    gemm_mma<0><<<dim3(FDIM / 128, RTILES, 1), 256, SMEM_TOTAL>>>(w1, b1);
    gemm_mma<1><<<dim3(DDIM / 128, RTILES, ZSPLIT), 256, SMEM_TOTAL>>>(w2, nullptr);
    finalize_kernel<<<NTOK, 256>>>(x, b2, out);
}